// round 9
// baseline (speedup 1.0000x reference)
#include <cuda_runtime.h>
#include <cuda_fp16.h>
#include <cstdint>

#define BB 64
#define TT 1024
#define II 512
#define HH 512
#define MM (BB*TT)              // 65536

#define ALPHA_LO 0.8187307530779818f   // exp(-1/5)
#define ALPHA_HI 0.9607894391523232f   // exp(-1/25)

// Device-global scratch (allocation-guard safe)
__device__ float  g_wx[(size_t)MM * HH];        // 128 MB
__device__ __half g_ah[(size_t)MM * II];        // 64 MB  x high half
__device__ __half g_al[(size_t)MM * II];        // 64 MB  x low  half
__device__ __half g_bh[(size_t)HH * II];        // 512 KB (2048*W) high
__device__ __half g_bl[(size_t)HH * II];        // 512 KB (2048*W) low

// ---------------------------------------------------------------------------
__device__ __forceinline__ uint32_t smem_u32(const void* p) {
    uint32_t a;
    asm("{ .reg .u64 t; cvta.to.shared.u64 t, %1; cvt.u32.u64 %0, t; }" : "=r"(a) : "l"(p));
    return a;
}
__device__ __forceinline__ void cp16(uint32_t dst, const void* src) {
    asm volatile("cp.async.cg.shared.global [%0], [%1], 16;" :: "r"(dst), "l"(src));
}
__device__ __forceinline__ void ldsm_x4(uint32_t* r, uint32_t addr) {
    asm volatile("ldmatrix.sync.aligned.m8n8.x4.shared.b16 {%0,%1,%2,%3}, [%4];"
                 : "=r"(r[0]), "=r"(r[1]), "=r"(r[2]), "=r"(r[3]) : "r"(addr));
}
__device__ __forceinline__ void mma16816(float* c, const uint32_t* a, uint32_t b0, uint32_t b1) {
    asm volatile(
        "mma.sync.aligned.m16n8k16.row.col.f32.f16.f16.f32 "
        "{%0,%1,%2,%3}, {%4,%5,%6,%7}, {%8,%9}, {%0,%1,%2,%3};"
        : "+f"(c[0]), "+f"(c[1]), "+f"(c[2]), "+f"(c[3])
        : "r"(a[0]), "r"(a[1]), "r"(a[2]), "r"(a[3]), "r"(b0), "r"(b1));
}

// ---------------------------------------------------------------------------
// Prep (merged): blocks [0, NA) split x into fp16 hi/lo; blocks [NA, NA+NB)
// split 2048*W. prep_b's 4us hides inside prep_a's memory time.
// ---------------------------------------------------------------------------
#define NA 16384    // MM*II/8/256
#define NB 256      // HH*II/4/256

__global__ __launch_bounds__(256)
void prep(const float* __restrict__ x, const float* __restrict__ W) {
    const int bid = blockIdx.x;
    if (bid < NA) {
        size_t i = ((size_t)bid * 256 + threadIdx.x) * 8;
        float4 v0 = *(const float4*)(x + i);
        float4 v1 = *(const float4*)(x + i + 4);
        float v[8] = {v0.x, v0.y, v0.z, v0.w, v1.x, v1.y, v1.z, v1.w};
        __half h[8], l[8];
        #pragma unroll
        for (int j = 0; j < 8; j++) {
            h[j] = __float2half_rn(v[j]);
            l[j] = __float2half_rn(v[j] - __half2float(h[j]));
        }
        *(uint4*)(g_ah + i) = *(uint4*)h;
        *(uint4*)(g_al + i) = *(uint4*)l;
    } else {
        size_t i = ((size_t)(bid - NA) * 256 + threadIdx.x) * 4;
        float4 v = *(const float4*)(W + i);
        float s[4] = {v.x * 2048.0f, v.y * 2048.0f, v.z * 2048.0f, v.w * 2048.0f};
        __half h[4], l[4];
        #pragma unroll
        for (int j = 0; j < 4; j++) {
            h[j] = __float2half_rn(s[j]);
            l[j] = __float2half_rn(s[j] - __half2float(h[j]));
        }
        *(uint2*)(g_bh + i) = *(uint2*)h;
        *(uint2*)(g_bl + i) = *(uint2*)l;
    }
}

// ---------------------------------------------------------------------------
// GEMM: Wx[m,n] = (xh.wh' + xh.wl' + xl.wh') / 2048  (w' = 2048*W)
// CTA tile 256m x 128n, 512 threads (16 warps: 8m x 2n, warp tile 32x64 --
// inner loop identical to validated R8). Fused 3-product chunks, BK=32,
// 16 chunks, 3-stage pipeline. Stage 48KB: ah16K | al16K | bh8K | bl8K.
// Fill traffic 1.07GB -> 786MB (LTS-bound => ~1.35x GEMM speedup).
// ---------------------------------------------------------------------------
#define BK 32
#define NST 3
#define STAGE 49152
#define OFF_AL 16384
#define OFF_BH 32768
#define OFF_BL 40960
#define NCHUNK 16

__global__ __launch_bounds__(512, 1)
void gemm_mma(void) {
    extern __shared__ char sm[];
    const uint32_t sbase = smem_u32(sm);
    const int tid  = threadIdx.x;
    const int lane = tid & 31;
    const int warp = tid >> 5;
    const int wm = warp & 7;          // 0..7 -> m offset 32*wm
    const int wn = warp >> 3;         // 0..1 -> n offset 64*wn
    const int m0 = blockIdx.y * 256;
    const int n0 = blockIdx.x * 128;

    // A cp.async mapping: r0a = tid>>1 (256 rows), 2 chunks from (tid&1)*2
    const int r0a = tid >> 1;
    const int ca  = (tid & 1) * 2;
    const int axr = (r0a >> 1) & 3;
    const uint32_t dA0 = (uint32_t)(r0a * 64 + ((ca + 0) ^ axr) * 16);
    const uint32_t dA1 = (uint32_t)(r0a * 64 + ((ca + 1) ^ axr) * 16);
    const size_t aoff = (size_t)(m0 + r0a) * II + ca * 8;

    // B cp.async mapping: r0b = tid>>2 (128 rows), 1 chunk cb = tid&3
    const int r0b = tid >> 2;
    const int cb  = tid & 3;
    const uint32_t dB = (uint32_t)(r0b * 64 + (cb ^ ((r0b >> 1) & 3)) * 16);
    const size_t boff = (size_t)(n0 + r0b) * II + cb * 8;

    float acc[2][8][4];
    #pragma unroll
    for (int i = 0; i < 2; i++)
        #pragma unroll
        for (int j = 0; j < 8; j++)
            #pragma unroll
            for (int q = 0; q < 4; q++) acc[i][j][q] = 0.0f;

    const int arow = wm * 32 + (lane & 15);
    const int ach  = lane >> 4;
    const int brow = wn * 64 + ((lane >> 4) << 3) + (lane & 7);
    const int bch  = (lane >> 3) & 1;

    auto issue = [&](int it) {
        const uint32_t stb = sbase + (uint32_t)(it % NST) * STAGE;
        const int kc = it * BK;
        cp16(stb + dA0, g_ah + aoff + kc);
        cp16(stb + dA1, g_ah + aoff + kc + 8);
        cp16(stb + OFF_AL + dA0, g_al + aoff + kc);
        cp16(stb + OFF_AL + dA1, g_al + aoff + kc + 8);
        cp16(stb + OFF_BH + dB, g_bh + boff + kc);
        cp16(stb + OFF_BL + dB, g_bl + boff + kc);
        asm volatile("cp.async.commit_group;");
    };

    issue(0);
    issue(1);

    for (int it = 0; it < NCHUNK; it++) {
        asm volatile("cp.async.wait_group %0;" :: "n"(1));
        __syncthreads();
        if (it + 2 < NCHUNK) issue(it + 2);
        else                 asm volatile("cp.async.commit_group;");

        const uint32_t St = sbase + (uint32_t)(it % NST) * STAGE;

        #pragma unroll
        for (int kk = 0; kk < 2; kk++) {
            const int c = kk * 2;

            uint32_t a_h[2][4], a_l[2][4];
            #pragma unroll
            for (int mi = 0; mi < 2; mi++) {
                const int row = arow + mi * 16;
                const uint32_t ro = (uint32_t)(row * 64 + (((c + ach) ^ ((row >> 1) & 3)) * 16));
                ldsm_x4(a_h[mi], St + ro);
                ldsm_x4(a_l[mi], St + OFF_AL + ro);
            }

            uint32_t b[4][4];
            #pragma unroll
            for (int g = 0; g < 4; g++) {
                const int row = brow + g * 16;
                ldsm_x4(b[g], St + OFF_BH + row * 64 + (((c + bch) ^ ((row >> 1) & 3)) * 16));
            }
            #pragma unroll
            for (int mi = 0; mi < 2; mi++)
                #pragma unroll
                for (int nj = 0; nj < 8; nj++)
                    mma16816(acc[mi][nj], a_h[mi], b[nj >> 1][(nj & 1) * 2],
                             b[nj >> 1][(nj & 1) * 2 + 1]);
            #pragma unroll
            for (int mi = 0; mi < 2; mi++)
                #pragma unroll
                for (int nj = 0; nj < 8; nj++)
                    mma16816(acc[mi][nj], a_l[mi], b[nj >> 1][(nj & 1) * 2],
                             b[nj >> 1][(nj & 1) * 2 + 1]);

            #pragma unroll
            for (int g = 0; g < 4; g++) {
                const int row = brow + g * 16;
                ldsm_x4(b[g], St + OFF_BL + row * 64 + (((c + bch) ^ ((row >> 1) & 3)) * 16));
            }
            #pragma unroll
            for (int mi = 0; mi < 2; mi++)
                #pragma unroll
                for (int nj = 0; nj < 8; nj++)
                    mma16816(acc[mi][nj], a_h[mi], b[nj >> 1][(nj & 1) * 2],
                             b[nj >> 1][(nj & 1) * 2 + 1]);
        }
    }

    const float inv = 1.0f / 2048.0f;
    #pragma unroll
    for (int mi = 0; mi < 2; mi++) {
        const int r = m0 + wm * 32 + mi * 16 + (lane >> 2);
        #pragma unroll
        for (int nj = 0; nj < 8; nj++) {
            const int c = n0 + wn * 64 + nj * 8 + 2 * (lane & 3);
            float* p0 = g_wx + (size_t)r * HH + c;
            float* p1 = g_wx + (size_t)(r + 8) * HH + c;
            *(float2*)p0 = make_float2(acc[mi][nj][0] * inv, acc[mi][nj][1] * inv);
            *(float2*)p1 = make_float2(acc[mi][nj][2] * inv, acc[mi][nj][3] * inv);
        }
    }
}

// ---------------------------------------------------------------------------
// LIF scan (R7-proven): 1 thread per (b,h), 32-deep static double buffer,
// streaming hints. 49.5us, ~4.4TB/s.
// ---------------------------------------------------------------------------
__global__ __launch_bounds__(128)
void lif_scan(const float* __restrict__ alpha,
              const float* __restrict__ u0,
              const float* __restrict__ s0,
              float* __restrict__ out) {
    const int g = blockIdx.x * 128 + threadIdx.x;
    const int b = g >> 9;
    const int h = g & 511;

    float al = alpha[h];
    al = fminf(fmaxf(al, ALPHA_LO), ALPHA_HI);
    const float ial = 1.0f - al;

    float u = u0[g];
    float s = s0[g];

    const float* p = g_wx + (size_t)b * TT * HH + h;
    float*       q = out  + (size_t)b * TT * HH + h;

    float wA[32], wB[32];
    #pragma unroll
    for (int j = 0; j < 32; j++) wA[j] = __ldcs(p + (size_t)j * HH);

    #pragma unroll 1
    for (int t = 0; t < TT; t += 64) {
        #pragma unroll
        for (int j = 0; j < 32; j++) wB[j] = __ldcs(p + (size_t)(t + 32 + j) * HH);
        #pragma unroll
        for (int j = 0; j < 32; j++) {
            u = fmaf(al, u - s, ial * wA[j]);
            s = (u - 1.0f > 0.0f) ? 1.0f : 0.0f;
            __stcs(q + (size_t)(t + j) * HH, s);
        }
        if (t + 64 < TT) {
            #pragma unroll
            for (int j = 0; j < 32; j++) wA[j] = __ldcs(p + (size_t)(t + 64 + j) * HH);
        }
        #pragma unroll
        for (int j = 0; j < 32; j++) {
            u = fmaf(al, u - s, ial * wB[j]);
            s = (u - 1.0f > 0.0f) ? 1.0f : 0.0f;
            __stcs(q + (size_t)(t + 32 + j) * HH, s);
        }
    }
}

// ---------------------------------------------------------------------------
extern "C" void kernel_launch(void* const* d_in, const int* in_sizes, int n_in,
                              void* d_out, int out_size) {
    const float* x     = (const float*)d_in[0];  // [B,T,I]
    const float* W     = (const float*)d_in[1];  // [H,I]
    const float* alpha = (const float*)d_in[2];  // [H]
    const float* u0    = (const float*)d_in[3];  // [B,H]
    const float* s0    = (const float*)d_in[4];  // [B,H]
    float* out = (float*)d_out;                  // [B,T,H]

    static bool attr_set = false;
    if (!attr_set) {
        cudaFuncSetAttribute(gemm_mma, cudaFuncAttributeMaxDynamicSharedMemorySize,
                             NST * STAGE);
        attr_set = true;
    }

    prep<<<NA + NB, 256>>>(x, W);

    dim3 grid(HH / 128, MM / 256);               // (4, 256) = 1024 CTAs
    gemm_mma<<<grid, 512, NST * STAGE>>>();

    lif_scan<<<(BB * HH) / 128, 128>>>(alpha, u0, s0, out);
}

// round 10
// speedup vs baseline: 1.1150x; 1.1150x over previous
#include <cuda_runtime.h>
#include <cuda_fp16.h>
#include <cstdint>

#define BB 64
#define TT 1024
#define II 512
#define HH 512
#define MM (BB*TT)              // 65536

#define ALPHA_LO 0.8187307530779818f   // exp(-1/5)
#define ALPHA_HI 0.9607894391523232f   // exp(-1/25)

// Device-global scratch (allocation-guard safe)
__device__ float  g_wx[(size_t)MM * HH];        // 128 MB
__device__ __half g_ah[(size_t)MM * II];        // 64 MB  x high half
__device__ __half g_al[(size_t)MM * II];        // 64 MB  x low  half
__device__ __half g_bh[(size_t)HH * II];        // 512 KB (2048*W) high
__device__ __half g_bl[(size_t)HH * II];        // 512 KB (2048*W) low

// ---------------------------------------------------------------------------
__device__ __forceinline__ uint32_t smem_u32(const void* p) {
    uint32_t a;
    asm("{ .reg .u64 t; cvta.to.shared.u64 t, %1; cvt.u32.u64 %0, t; }" : "=r"(a) : "l"(p));
    return a;
}
__device__ __forceinline__ void cp16(uint32_t dst, const void* src) {
    asm volatile("cp.async.cg.shared.global [%0], [%1], 16;" :: "r"(dst), "l"(src));
}
__device__ __forceinline__ void ldsm_x4(uint32_t* r, uint32_t addr) {
    asm volatile("ldmatrix.sync.aligned.m8n8.x4.shared.b16 {%0,%1,%2,%3}, [%4];"
                 : "=r"(r[0]), "=r"(r[1]), "=r"(r[2]), "=r"(r[3]) : "r"(addr));
}
__device__ __forceinline__ void mma16816(float* c, const uint32_t* a, uint32_t b0, uint32_t b1) {
    asm volatile(
        "mma.sync.aligned.m16n8k16.row.col.f32.f16.f16.f32 "
        "{%0,%1,%2,%3}, {%4,%5,%6,%7}, {%8,%9}, {%0,%1,%2,%3};"
        : "+f"(c[0]), "+f"(c[1]), "+f"(c[2]), "+f"(c[3])
        : "r"(a[0]), "r"(a[1]), "r"(a[2]), "r"(a[3]), "r"(b0), "r"(b1));
}

// ---------------------------------------------------------------------------
// Prep (merged, R9-proven 37us): blocks [0, NA) split x into fp16 hi/lo;
// blocks [NA, NA+NB) split 2048*W.
// ---------------------------------------------------------------------------
#define NA 16384    // MM*II/8/256
#define NB 256      // HH*II/4/256

__global__ __launch_bounds__(256)
void prep(const float* __restrict__ x, const float* __restrict__ W) {
    const int bid = blockIdx.x;
    if (bid < NA) {
        size_t i = ((size_t)bid * 256 + threadIdx.x) * 8;
        float4 v0 = *(const float4*)(x + i);
        float4 v1 = *(const float4*)(x + i + 4);
        float v[8] = {v0.x, v0.y, v0.z, v0.w, v1.x, v1.y, v1.z, v1.w};
        __half h[8], l[8];
        #pragma unroll
        for (int j = 0; j < 8; j++) {
            h[j] = __float2half_rn(v[j]);
            l[j] = __float2half_rn(v[j] - __half2float(h[j]));
        }
        *(uint4*)(g_ah + i) = *(uint4*)h;
        *(uint4*)(g_al + i) = *(uint4*)l;
    } else {
        size_t i = ((size_t)(bid - NA) * 256 + threadIdx.x) * 4;
        float4 v = *(const float4*)(W + i);
        float s[4] = {v.x * 2048.0f, v.y * 2048.0f, v.z * 2048.0f, v.w * 2048.0f};
        __half h[4], l[4];
        #pragma unroll
        for (int j = 0; j < 4; j++) {
            h[j] = __float2half_rn(s[j]);
            l[j] = __float2half_rn(s[j] - __half2float(h[j]));
        }
        *(uint2*)(g_bh + i) = *(uint2*)h;
        *(uint2*)(g_bl + i) = *(uint2*)l;
    }
}

// ---------------------------------------------------------------------------
// GEMM (R8-exact, proven 227us): Wx = (xh.wh' + xh.wl' + xl.wh') / 2048
// CTA 128x128, 256 threads (8 warps 4m x 2n, warp tile 32x64), fused
// 3-product chunks, BK=32, 16 chunks, 3-stage pipeline, 2 CTAs/SM.
// ---------------------------------------------------------------------------
#define BK 32
#define NST 3
#define STAGE 32768       // ah 8K | al 8K | bh 8K | bl 8K
#define NCHUNK 16

__global__ __launch_bounds__(256, 2)
void gemm_mma(void) {
    extern __shared__ char sm[];
    const uint32_t sbase = smem_u32(sm);
    const int tid  = threadIdx.x;
    const int lane = tid & 31;
    const int warp = tid >> 5;
    const int wm = warp & 3;
    const int wn = warp >> 2;
    const int m0 = blockIdx.y * 128;
    const int n0 = blockIdx.x * 128;

    const int r0 = tid >> 2;
    const int ch = tid & 3;
    const int phys = ch ^ ((r0 >> 1) & 3);
    const uint32_t d0 = (uint32_t)(r0 * 64 + phys * 16);
    const uint32_t d1 = d0 + 64 * 64;

    float acc[2][8][4];
    #pragma unroll
    for (int i = 0; i < 2; i++)
        #pragma unroll
        for (int j = 0; j < 8; j++)
            #pragma unroll
            for (int q = 0; q < 4; q++) acc[i][j][q] = 0.0f;

    const int arow = wm * 32 + (lane & 15);
    const int ach  = lane >> 4;
    const int brow = wn * 64 + ((lane >> 4) << 3) + (lane & 7);
    const int bch  = (lane >> 3) & 1;

    const size_t aoff = (size_t)(m0 + r0) * II + ch * 8;
    const size_t boff = (size_t)(n0 + r0) * II + ch * 8;

    auto issue = [&](int it) {
        const uint32_t stb = sbase + (uint32_t)(it % NST) * STAGE;
        const int kc = it * BK;
        const __half* s;
        s = g_ah + aoff + kc;
        cp16(stb + d0, s);  cp16(stb + d1, s + (size_t)64 * II);
        s = g_al + aoff + kc;
        cp16(stb + 8192 + d0, s);  cp16(stb + 8192 + d1, s + (size_t)64 * II);
        s = g_bh + boff + kc;
        cp16(stb + 16384 + d0, s); cp16(stb + 16384 + d1, s + (size_t)64 * II);
        s = g_bl + boff + kc;
        cp16(stb + 24576 + d0, s); cp16(stb + 24576 + d1, s + (size_t)64 * II);
        asm volatile("cp.async.commit_group;");
    };

    issue(0);
    issue(1);

    for (int it = 0; it < NCHUNK; it++) {
        asm volatile("cp.async.wait_group %0;" :: "n"(1));
        __syncthreads();
        if (it + 2 < NCHUNK) issue(it + 2);
        else                 asm volatile("cp.async.commit_group;");

        const uint32_t St = sbase + (uint32_t)(it % NST) * STAGE;

        #pragma unroll
        for (int kk = 0; kk < 2; kk++) {
            const int c = kk * 2;

            uint32_t a_h[2][4], a_l[2][4];
            #pragma unroll
            for (int mi = 0; mi < 2; mi++) {
                const int row = arow + mi * 16;
                const uint32_t ro = (uint32_t)(row * 64 + (((c + ach) ^ ((row >> 1) & 3)) * 16));
                ldsm_x4(a_h[mi], St + ro);
                ldsm_x4(a_l[mi], St + 8192 + ro);
            }

            uint32_t b[4][4];
            #pragma unroll
            for (int g = 0; g < 4; g++) {
                const int row = brow + g * 16;
                ldsm_x4(b[g], St + 16384 + row * 64 + (((c + bch) ^ ((row >> 1) & 3)) * 16));
            }
            #pragma unroll
            for (int mi = 0; mi < 2; mi++)
                #pragma unroll
                for (int nj = 0; nj < 8; nj++)
                    mma16816(acc[mi][nj], a_h[mi], b[nj >> 1][(nj & 1) * 2],
                             b[nj >> 1][(nj & 1) * 2 + 1]);
            #pragma unroll
            for (int mi = 0; mi < 2; mi++)
                #pragma unroll
                for (int nj = 0; nj < 8; nj++)
                    mma16816(acc[mi][nj], a_l[mi], b[nj >> 1][(nj & 1) * 2],
                             b[nj >> 1][(nj & 1) * 2 + 1]);

            #pragma unroll
            for (int g = 0; g < 4; g++) {
                const int row = brow + g * 16;
                ldsm_x4(b[g], St + 24576 + row * 64 + (((c + bch) ^ ((row >> 1) & 3)) * 16));
            }
            #pragma unroll
            for (int mi = 0; mi < 2; mi++)
                #pragma unroll
                for (int nj = 0; nj < 8; nj++)
                    mma16816(acc[mi][nj], a_h[mi], b[nj >> 1][(nj & 1) * 2],
                             b[nj >> 1][(nj & 1) * 2 + 1]);
        }
    }

    const float inv = 1.0f / 2048.0f;
    #pragma unroll
    for (int mi = 0; mi < 2; mi++) {
        const int r = m0 + wm * 32 + mi * 16 + (lane >> 2);
        #pragma unroll
        for (int nj = 0; nj < 8; nj++) {
            const int c = n0 + wn * 64 + nj * 8 + 2 * (lane & 3);
            float* p0 = g_wx + (size_t)r * HH + c;
            float* p1 = g_wx + (size_t)(r + 8) * HH + c;
            *(float2*)p0 = make_float2(acc[mi][nj][0] * inv, acc[mi][nj][1] * inv);
            *(float2*)p1 = make_float2(acc[mi][nj][2] * inv, acc[mi][nj][3] * inv);
        }
    }
}

// ---------------------------------------------------------------------------
// LIF scan: 1 thread per (b,h), 40-deep static double buffer (5.2 MB in
// flight chip-wide), streaming hints. T=1024 = 12 full 80-step iters + 64.
// ---------------------------------------------------------------------------
#define SD 40

__global__ __launch_bounds__(128)
void lif_scan(const float* __restrict__ alpha,
              const float* __restrict__ u0,
              const float* __restrict__ s0,
              float* __restrict__ out) {
    const int g = blockIdx.x * 128 + threadIdx.x;
    const int b = g >> 9;
    const int h = g & 511;

    float al = alpha[h];
    al = fminf(fmaxf(al, ALPHA_LO), ALPHA_HI);
    const float ial = 1.0f - al;

    float u = u0[g];
    float s = s0[g];

    const float* p = g_wx + (size_t)b * TT * HH + h;
    float*       q = out  + (size_t)b * TT * HH + h;

    float wA[SD], wB[SD];
    #pragma unroll
    for (int j = 0; j < SD; j++) wA[j] = __ldcs(p + (size_t)j * HH);

    // 1024 = 12*80 + 64: loop over 12 double-iters, then a 64-step tail.
    #pragma unroll 1
    for (int t = 0; t < 960; t += 2 * SD) {
        #pragma unroll
        for (int j = 0; j < SD; j++) wB[j] = __ldcs(p + (size_t)(t + SD + j) * HH);
        #pragma unroll
        for (int j = 0; j < SD; j++) {
            u = fmaf(al, u - s, ial * wA[j]);
            s = (u - 1.0f > 0.0f) ? 1.0f : 0.0f;
            __stcs(q + (size_t)(t + j) * HH, s);
        }
        #pragma unroll
        for (int j = 0; j < SD; j++) wA[j] = __ldcs(p + (size_t)(t + 2 * SD + j) * HH);
        #pragma unroll
        for (int j = 0; j < SD; j++) {
            u = fmaf(al, u - s, ial * wB[j]);
            s = (u - 1.0f > 0.0f) ? 1.0f : 0.0f;
            __stcs(q + (size_t)(t + SD + j) * HH, s);
        }
    }
    // tail: t in [960, 1024): wA holds [960, 1000); load [1000, 1024)
    {
        float wT[24];
        #pragma unroll
        for (int j = 0; j < 24; j++) wT[j] = __ldcs(p + (size_t)(1000 + j) * HH);
        #pragma unroll
        for (int j = 0; j < SD; j++) {
            u = fmaf(al, u - s, ial * wA[j]);
            s = (u - 1.0f > 0.0f) ? 1.0f : 0.0f;
            __stcs(q + (size_t)(960 + j) * HH, s);
        }
        #pragma unroll
        for (int j = 0; j < 24; j++) {
            u = fmaf(al, u - s, ial * wT[j]);
            s = (u - 1.0f > 0.0f) ? 1.0f : 0.0f;
            __stcs(q + (size_t)(1000 + j) * HH, s);
        }
    }
}

// ---------------------------------------------------------------------------
extern "C" void kernel_launch(void* const* d_in, const int* in_sizes, int n_in,
                              void* d_out, int out_size) {
    const float* x     = (const float*)d_in[0];  // [B,T,I]
    const float* W     = (const float*)d_in[1];  // [H,I]
    const float* alpha = (const float*)d_in[2];  // [H]
    const float* u0    = (const float*)d_in[3];  // [B,H]
    const float* s0    = (const float*)d_in[4];  // [B,H]
    float* out = (float*)d_out;                  // [B,T,H]

    static bool attr_set = false;
    if (!attr_set) {
        cudaFuncSetAttribute(gemm_mma, cudaFuncAttributeMaxDynamicSharedMemorySize,
                             NST * STAGE);
        attr_set = true;
    }

    prep<<<NA + NB, 256>>>(x, W);

    dim3 grid(HH / 128, MM / 128);               // (4, 512) = 2048 CTAs
    gemm_mma<<<grid, 256, NST * STAGE>>>();

    lif_scan<<<(BB * HH) / 128, 128>>>(alpha, u0, s0, out);
}

// round 11
// speedup vs baseline: 1.1261x; 1.0100x over previous
#include <cuda_runtime.h>
#include <cuda_fp16.h>
#include <cstdint>

#define BB 64
#define TT 1024
#define II 512
#define HH 512
#define MM (BB*TT)              // 65536

#define ALPHA_LO 0.8187307530779818f   // exp(-1/5)
#define ALPHA_HI 0.9607894391523232f   // exp(-1/25)

// Device-global scratch (allocation-guard safe)
__device__ float  g_wx[(size_t)MM * HH];        // 128 MB
__device__ __half g_ah[(size_t)MM * II];        // 64 MB  x high half
__device__ __half g_al[(size_t)MM * II];        // 64 MB  x low  half
__device__ __half g_bh[(size_t)HH * II];        // 512 KB (2048*W) high
__device__ __half g_bl[(size_t)HH * II];        // 512 KB (2048*W) low

// ---------------------------------------------------------------------------
__device__ __forceinline__ uint32_t smem_u32(const void* p) {
    uint32_t a;
    asm("{ .reg .u64 t; cvta.to.shared.u64 t, %1; cvt.u32.u64 %0, t; }" : "=r"(a) : "l"(p));
    return a;
}
__device__ __forceinline__ void cp16(uint32_t dst, const void* src) {
    asm volatile("cp.async.cg.shared.global [%0], [%1], 16;" :: "r"(dst), "l"(src));
}
__device__ __forceinline__ void ldsm_x4(uint32_t* r, uint32_t addr) {
    asm volatile("ldmatrix.sync.aligned.m8n8.x4.shared.b16 {%0,%1,%2,%3}, [%4];"
                 : "=r"(r[0]), "=r"(r[1]), "=r"(r[2]), "=r"(r[3]) : "r"(addr));
}
__device__ __forceinline__ void mma16816(float* c, const uint32_t* a, uint32_t b0, uint32_t b1) {
    asm volatile(
        "mma.sync.aligned.m16n8k16.row.col.f32.f16.f16.f32 "
        "{%0,%1,%2,%3}, {%4,%5,%6,%7}, {%8,%9}, {%0,%1,%2,%3};"
        : "+f"(c[0]), "+f"(c[1]), "+f"(c[2]), "+f"(c[3])
        : "r"(a[0]), "r"(a[1]), "r"(a[2]), "r"(a[3]), "r"(b0), "r"(b1));
}

// ---------------------------------------------------------------------------
// Prep (merged, proven 37us): blocks [0, NA) split x into fp16 hi/lo;
// blocks [NA, NA+NB) split 2048*W.
// ---------------------------------------------------------------------------
#define NA 16384    // MM*II/8/256
#define NB 256      // HH*II/4/256

__global__ __launch_bounds__(256)
void prep(const float* __restrict__ x, const float* __restrict__ W) {
    const int bid = blockIdx.x;
    if (bid < NA) {
        size_t i = ((size_t)bid * 256 + threadIdx.x) * 8;
        float4 v0 = *(const float4*)(x + i);
        float4 v1 = *(const float4*)(x + i + 4);
        float v[8] = {v0.x, v0.y, v0.z, v0.w, v1.x, v1.y, v1.z, v1.w};
        __half h[8], l[8];
        #pragma unroll
        for (int j = 0; j < 8; j++) {
            h[j] = __float2half_rn(v[j]);
            l[j] = __float2half_rn(v[j] - __half2float(h[j]));
        }
        *(uint4*)(g_ah + i) = *(uint4*)h;
        *(uint4*)(g_al + i) = *(uint4*)l;
    } else {
        size_t i = ((size_t)(bid - NA) * 256 + threadIdx.x) * 4;
        float4 v = *(const float4*)(W + i);
        float s[4] = {v.x * 2048.0f, v.y * 2048.0f, v.z * 2048.0f, v.w * 2048.0f};
        __half h[4], l[4];
        #pragma unroll
        for (int j = 0; j < 4; j++) {
            h[j] = __float2half_rn(s[j]);
            l[j] = __float2half_rn(s[j] - __half2float(h[j]));
        }
        *(uint2*)(g_bh + i) = *(uint2*)h;
        *(uint2*)(g_bl + i) = *(uint2*)l;
    }
}

// ---------------------------------------------------------------------------
// GEMM (R8-exact, proven 227us): Wx = (xh.wh' + xh.wl' + xl.wh') / 2048
// CTA 128x128, 256 threads (8 warps 4m x 2n, warp tile 32x64), fused
// 3-product chunks, BK=32, 16 chunks, 3-stage pipeline, 2 CTAs/SM.
// ---------------------------------------------------------------------------
#define BK 32
#define NST 3
#define STAGE 32768       // ah 8K | al 8K | bh 8K | bl 8K
#define NCHUNK 16

__global__ __launch_bounds__(256, 2)
void gemm_mma(void) {
    extern __shared__ char sm[];
    const uint32_t sbase = smem_u32(sm);
    const int tid  = threadIdx.x;
    const int lane = tid & 31;
    const int warp = tid >> 5;
    const int wm = warp & 3;
    const int wn = warp >> 2;
    const int m0 = blockIdx.y * 128;
    const int n0 = blockIdx.x * 128;

    const int r0 = tid >> 2;
    const int ch = tid & 3;
    const int phys = ch ^ ((r0 >> 1) & 3);
    const uint32_t d0 = (uint32_t)(r0 * 64 + phys * 16);
    const uint32_t d1 = d0 + 64 * 64;

    float acc[2][8][4];
    #pragma unroll
    for (int i = 0; i < 2; i++)
        #pragma unroll
        for (int j = 0; j < 8; j++)
            #pragma unroll
            for (int q = 0; q < 4; q++) acc[i][j][q] = 0.0f;

    const int arow = wm * 32 + (lane & 15);
    const int ach  = lane >> 4;
    const int brow = wn * 64 + ((lane >> 4) << 3) + (lane & 7);
    const int bch  = (lane >> 3) & 1;

    const size_t aoff = (size_t)(m0 + r0) * II + ch * 8;
    const size_t boff = (size_t)(n0 + r0) * II + ch * 8;

    auto issue = [&](int it) {
        const uint32_t stb = sbase + (uint32_t)(it % NST) * STAGE;
        const int kc = it * BK;
        const __half* s;
        s = g_ah + aoff + kc;
        cp16(stb + d0, s);  cp16(stb + d1, s + (size_t)64 * II);
        s = g_al + aoff + kc;
        cp16(stb + 8192 + d0, s);  cp16(stb + 8192 + d1, s + (size_t)64 * II);
        s = g_bh + boff + kc;
        cp16(stb + 16384 + d0, s); cp16(stb + 16384 + d1, s + (size_t)64 * II);
        s = g_bl + boff + kc;
        cp16(stb + 24576 + d0, s); cp16(stb + 24576 + d1, s + (size_t)64 * II);
        asm volatile("cp.async.commit_group;");
    };

    issue(0);
    issue(1);

    for (int it = 0; it < NCHUNK; it++) {
        asm volatile("cp.async.wait_group %0;" :: "n"(1));
        __syncthreads();
        if (it + 2 < NCHUNK) issue(it + 2);
        else                 asm volatile("cp.async.commit_group;");

        const uint32_t St = sbase + (uint32_t)(it % NST) * STAGE;

        #pragma unroll
        for (int kk = 0; kk < 2; kk++) {
            const int c = kk * 2;

            uint32_t a_h[2][4], a_l[2][4];
            #pragma unroll
            for (int mi = 0; mi < 2; mi++) {
                const int row = arow + mi * 16;
                const uint32_t ro = (uint32_t)(row * 64 + (((c + ach) ^ ((row >> 1) & 3)) * 16));
                ldsm_x4(a_h[mi], St + ro);
                ldsm_x4(a_l[mi], St + 8192 + ro);
            }

            uint32_t b[4][4];
            #pragma unroll
            for (int g = 0; g < 4; g++) {
                const int row = brow + g * 16;
                ldsm_x4(b[g], St + 16384 + row * 64 + (((c + bch) ^ ((row >> 1) & 3)) * 16));
            }
            #pragma unroll
            for (int mi = 0; mi < 2; mi++)
                #pragma unroll
                for (int nj = 0; nj < 8; nj++)
                    mma16816(acc[mi][nj], a_h[mi], b[nj >> 1][(nj & 1) * 2],
                             b[nj >> 1][(nj & 1) * 2 + 1]);
            #pragma unroll
            for (int mi = 0; mi < 2; mi++)
                #pragma unroll
                for (int nj = 0; nj < 8; nj++)
                    mma16816(acc[mi][nj], a_l[mi], b[nj >> 1][(nj & 1) * 2],
                             b[nj >> 1][(nj & 1) * 2 + 1]);

            #pragma unroll
            for (int g = 0; g < 4; g++) {
                const int row = brow + g * 16;
                ldsm_x4(b[g], St + 24576 + row * 64 + (((c + bch) ^ ((row >> 1) & 3)) * 16));
            }
            #pragma unroll
            for (int mi = 0; mi < 2; mi++)
                #pragma unroll
                for (int nj = 0; nj < 8; nj++)
                    mma16816(acc[mi][nj], a_h[mi], b[nj >> 1][(nj & 1) * 2],
                             b[nj >> 1][(nj & 1) * 2 + 1]);
        }
    }

    const float inv = 1.0f / 2048.0f;
    #pragma unroll
    for (int mi = 0; mi < 2; mi++) {
        const int r = m0 + wm * 32 + mi * 16 + (lane >> 2);
        #pragma unroll
        for (int nj = 0; nj < 8; nj++) {
            const int c = n0 + wn * 64 + nj * 8 + 2 * (lane & 3);
            float* p0 = g_wx + (size_t)r * HH + c;
            float* p1 = g_wx + (size_t)(r + 8) * HH + c;
            *(float2*)p0 = make_float2(acc[mi][nj][0] * inv, acc[mi][nj][1] * inv);
            *(float2*)p1 = make_float2(acc[mi][nj][2] * inv, acc[mi][nj][3] * inv);
        }
    }
}

// ---------------------------------------------------------------------------
// LIF scan (R7-exact, proven 49.5us): 1 thread per (b,h), 32-deep static
// double buffer (80 buffer regs, no spill), streaming hints.
// ---------------------------------------------------------------------------
__global__ __launch_bounds__(128)
void lif_scan(const float* __restrict__ alpha,
              const float* __restrict__ u0,
              const float* __restrict__ s0,
              float* __restrict__ out) {
    const int g = blockIdx.x * 128 + threadIdx.x;
    const int b = g >> 9;
    const int h = g & 511;

    float al = alpha[h];
    al = fminf(fmaxf(al, ALPHA_LO), ALPHA_HI);
    const float ial = 1.0f - al;

    float u = u0[g];
    float s = s0[g];

    const float* p = g_wx + (size_t)b * TT * HH + h;
    float*       q = out  + (size_t)b * TT * HH + h;

    float wA[32], wB[32];
    #pragma unroll
    for (int j = 0; j < 32; j++) wA[j] = __ldcs(p + (size_t)j * HH);

    #pragma unroll 1
    for (int t = 0; t < TT; t += 64) {
        #pragma unroll
        for (int j = 0; j < 32; j++) wB[j] = __ldcs(p + (size_t)(t + 32 + j) * HH);
        #pragma unroll
        for (int j = 0; j < 32; j++) {
            u = fmaf(al, u - s, ial * wA[j]);
            s = (u - 1.0f > 0.0f) ? 1.0f : 0.0f;
            __stcs(q + (size_t)(t + j) * HH, s);
        }
        if (t + 64 < TT) {
            #pragma unroll
            for (int j = 0; j < 32; j++) wA[j] = __ldcs(p + (size_t)(t + 64 + j) * HH);
        }
        #pragma unroll
        for (int j = 0; j < 32; j++) {
            u = fmaf(al, u - s, ial * wB[j]);
            s = (u - 1.0f > 0.0f) ? 1.0f : 0.0f;
            __stcs(q + (size_t)(t + 32 + j) * HH, s);
        }
    }
}

// ---------------------------------------------------------------------------
extern "C" void kernel_launch(void* const* d_in, const int* in_sizes, int n_in,
                              void* d_out, int out_size) {
    const float* x     = (const float*)d_in[0];  // [B,T,I]
    const float* W     = (const float*)d_in[1];  // [H,I]
    const float* alpha = (const float*)d_in[2];  // [H]
    const float* u0    = (const float*)d_in[3];  // [B,H]
    const float* s0    = (const float*)d_in[4];  // [B,H]
    float* out = (float*)d_out;                  // [B,T,H]

    static bool attr_set = false;
    if (!attr_set) {
        cudaFuncSetAttribute(gemm_mma, cudaFuncAttributeMaxDynamicSharedMemorySize,
                             NST * STAGE);
        attr_set = true;
    }

    prep<<<NA + NB, 256>>>(x, W);

    dim3 grid(HH / 128, MM / 128);               // (4, 512) = 2048 CTAs
    gemm_mma<<<grid, 256, NST * STAGE>>>();

    lif_scan<<<(BB * HH) / 128, 128>>>(alpha, u0, s0, out);
}